// round 6
// baseline (speedup 1.0000x reference)
#include <cuda_runtime.h>

#define B_   32
#define C_   4
#define N_   16384
#define RES_ 32
#define NVOX (B_ * RES_ * RES_ * RES_)    // 1048576
#define NB   2048                         // refl blocks: 64 per batch, 256 pts each

// Scratch (allocation-free): padded float4 copy of voxel_grid_cp -> LDG.128 gathers.
__device__ float4 g_cp_pad[NVOX];         // 16 MB
__device__ float  g_partials[NB];
__device__ int    g_count = 0;            // reset to 0 by last block each run

// ---------------------------------------------------------------------------
// Pad voxel_grid_cp [B,32,32,32,3] -> float4 (4 voxels / thread, all LDG/STG.128).
// ---------------------------------------------------------------------------
__global__ void __launch_bounds__(256) pad_kernel(const float4* __restrict__ cp4) {
    int i = blockIdx.x * 256 + threadIdx.x;      // 0 .. NVOX/4-1
    float4 a = cp4[3 * i + 0];
    float4 b = cp4[3 * i + 1];
    float4 c = cp4[3 * i + 2];
    g_cp_pad[4 * i + 0] = make_float4(a.x, a.y, a.z, 0.0f);
    g_cp_pad[4 * i + 1] = make_float4(a.w, b.x, b.y, 0.0f);
    g_cp_pad[4 * i + 2] = make_float4(b.z, b.w, c.x, 0.0f);
    g_cp_pad[4 * i + 3] = make_float4(c.y, c.z, c.w, 0.0f);
}

// ---------------------------------------------------------------------------
// Main: 1 point/thread, 4 planes; gather cp via LDG.128; fused final reduce.
// Completion protocol: release-atomic counter (NO per-block gpu fence -> no
// L1D flush), single acquire fence + L2 (.cg) partial loads in the last block.
// ---------------------------------------------------------------------------
__global__ void __launch_bounds__(256) refl_kernel(const float* __restrict__ y_pred,
                                                   const float* __restrict__ points,
                                                   float* __restrict__ out) {
    const int b  = blockIdx.x >> 6;               // 64 blocks per batch
    const int n0 = (blockIdx.x & 63) << 8;        // first point of this block

    __shared__ float4 plane[4];                   // n_hat.xyz, d
    __shared__ float  spts[768];                  // 256 points * xyz
    if (threadIdx.x < 4) {
        const float* yp = y_pred + (b * 4 + threadIdx.x) * 4;
        float nx = yp[0], ny = yp[1], nz = yp[2];
        float inv = rsqrtf(nx*nx + ny*ny + nz*nz);
        plane[threadIdx.x] = make_float4(nx*inv, ny*inv, nz*inv, yp[3]);
    }
    // Stage this block's 256 points (768 floats = 192 float4, 16B-aligned).
    if (threadIdx.x < 192) {
        const float4* src = (const float4*)(points + ((size_t)b * N_ + n0) * 3);
        ((float4*)spts)[threadIdx.x] = src[threadIdx.x];
    }
    __syncthreads();

    const float px = spts[3 * threadIdx.x + 0];
    const float py = spts[3 * threadIdx.x + 1];
    const float pz = spts[3 * threadIdx.x + 2];

    const float4* cpb = g_cp_pad + (b << 15);     // b * 32768
    float acc = 0.0f;
#pragma unroll
    for (int c = 0; c < 4; c++) {
        float4 pl = plane[c];
        float t  = 2.0f * (px*pl.x + py*pl.y + pz*pl.z + pl.w);
        float rx = fmaf(-t, pl.x, px);
        float ry = fmaf(-t, pl.y, py);
        float rz = fmaf(-t, pl.z, pz);
        int v0 = min(RES_ - 1, max(0, __float2int_rd(rx * (float)RES_)));
        int v1 = min(RES_ - 1, max(0, __float2int_rd(ry * (float)RES_)));
        int v2 = min(RES_ - 1, max(0, __float2int_rd(rz * (float)RES_)));
        float4 cpv = __ldg(&cpb[(v0 << 10) | (v1 << 5) | v2]);
        float dx = rx - cpv.x, dy = ry - cpv.y, dz = rz - cpv.z;
        acc += sqrtf(fmaf(dx, dx, fmaf(dy, dy, dz * dz)));
    }

    // Deterministic block reduction (fixed order), no float atomics.
#pragma unroll
    for (int off = 16; off >= 1; off >>= 1)
        acc += __shfl_xor_sync(0xffffffffu, acc, off);
    __shared__ float ws[8];
    const int wid = threadIdx.x >> 5;
    if ((threadIdx.x & 31) == 0) ws[wid] = acc;
    __syncthreads();

    __shared__ bool is_last;
    if (threadIdx.x == 0) {
        float s = 0.0f;
#pragma unroll
        for (int w = 0; w < 8; w++) s += ws[w];
        // L2 store of the partial, then RELEASE atomic: orders the store
        // without a gpu-scope fence (no CCTL.IVALL / L1 flush).
        asm volatile("st.global.cg.f32 [%0], %1;"
                     :: "l"(&g_partials[blockIdx.x]), "f"(s) : "memory");
        int done;
        asm volatile("atom.release.gpu.global.add.s32 %0, [%1], 1;"
                     : "=r"(done) : "l"(&g_count) : "memory");
        is_last = (done == NB - 1);
    }
    __syncthreads();
    if (!is_last) return;

    // ---- last block only: acquire, then final deterministic reduction ----
    asm volatile("fence.acq_rel.gpu;" ::: "memory");

    // Regularizer: 25 * mean_b ||n_hat n_hat^T - I||_F  (warp 0, one lane/batch)
    __shared__ float reg_s;
    if (threadIdx.x < 32) {
        const float* yp = y_pred + threadIdx.x * 16;
        float nh[4][3];
#pragma unroll
        for (int c = 0; c < 4; c++) {
            float nx = yp[c*4+0], ny = yp[c*4+1], nz = yp[c*4+2];
            float inv = rsqrtf(nx*nx + ny*ny + nz*nz);
            nh[c][0] = nx*inv; nh[c][1] = ny*inv; nh[c][2] = nz*inv;
        }
        float s = 0.0f;
#pragma unroll
        for (int c = 0; c < 4; c++)
#pragma unroll
            for (int e = 0; e < 4; e++) {
                float g = nh[c][0]*nh[e][0] + nh[c][1]*nh[e][1] + nh[c][2]*nh[e][2]
                          - (c == e ? 1.0f : 0.0f);
                s += g * g;
            }
        float reg = sqrtf(s);
#pragma unroll
        for (int off = 16; off >= 1; off >>= 1)
            reg += __shfl_xor_sync(0xffffffffu, reg, off);
        if (threadIdx.x == 0) reg_s = 25.0f * reg * (1.0f / (float)B_);
    }

    // Sum all 2048 partials in fixed order, reading via L2 (.cg).
    __shared__ float red[256];
    float a0, a1, a2, a3, a4, a5, a6, a7;
    {
        const float* p = g_partials;
        int i = threadIdx.x;
        asm volatile("ld.global.cg.f32 %0, [%1];" : "=f"(a0) : "l"(p + i));
        asm volatile("ld.global.cg.f32 %0, [%1];" : "=f"(a1) : "l"(p + i + 256));
        asm volatile("ld.global.cg.f32 %0, [%1];" : "=f"(a2) : "l"(p + i + 512));
        asm volatile("ld.global.cg.f32 %0, [%1];" : "=f"(a3) : "l"(p + i + 768));
        asm volatile("ld.global.cg.f32 %0, [%1];" : "=f"(a4) : "l"(p + i + 1024));
        asm volatile("ld.global.cg.f32 %0, [%1];" : "=f"(a5) : "l"(p + i + 1280));
        asm volatile("ld.global.cg.f32 %0, [%1];" : "=f"(a6) : "l"(p + i + 1536));
        asm volatile("ld.global.cg.f32 %0, [%1];" : "=f"(a7) : "l"(p + i + 1792));
    }
    red[threadIdx.x] = ((a0 + a1) + (a2 + a3)) + ((a4 + a5) + (a6 + a7));
    __syncthreads();
#pragma unroll
    for (int stride = 128; stride >= 1; stride >>= 1) {
        if (threadIdx.x < stride) red[threadIdx.x] += red[threadIdx.x + stride];
        __syncthreads();
    }
    if (threadIdx.x == 0) {
        out[0]  = red[0] * (1.0f / (float)N_) + reg_s;
        g_count = 0;                               // reset for next graph replay
    }
}

extern "C" void kernel_launch(void* const* d_in, const int* in_sizes, int n_in,
                              void* d_out, int out_size) {
    const float* y_pred = (const float*)d_in[0];
    const float* points = (const float*)d_in[1];
    // d_in[2] = voxel_grid — unused by the reference math.
    const float4* cp4   = (const float4*)d_in[3];
    float* out = (float*)d_out;

    pad_kernel<<<NVOX / 4 / 256, 256>>>(cp4);
    refl_kernel<<<NB, 256>>>(y_pred, points, out);
}

// round 7
// speedup vs baseline: 1.0356x; 1.0356x over previous
#include <cuda_runtime.h>

#define B_   32
#define C_   4
#define N_   16384
#define RES_ 32
#define NVOX (B_ * RES_ * RES_ * RES_)    // 1048576
#define NB   1024                         // refl blocks: 32 per batch, 512 pts each

// Scratch (allocation-free): padded float4 copy of voxel_grid_cp -> LDG.128 gathers.
__device__ float4 g_cp_pad[NVOX];         // 16 MB
__device__ float  g_partials[NB];
__device__ int    g_count = 0;            // reset to 0 by last block each run

// ---------------------------------------------------------------------------
// Pad voxel_grid_cp [B,32,32,32,3] -> float4 (4 voxels / thread, all LDG/STG.128).
// ---------------------------------------------------------------------------
__global__ void __launch_bounds__(256) pad_kernel(const float4* __restrict__ cp4) {
    int i = blockIdx.x * 256 + threadIdx.x;      // 0 .. NVOX/4-1
    float4 a = cp4[3 * i + 0];
    float4 b = cp4[3 * i + 1];
    float4 c = cp4[3 * i + 2];
    g_cp_pad[4 * i + 0] = make_float4(a.x, a.y, a.z, 0.0f);
    g_cp_pad[4 * i + 1] = make_float4(a.w, b.x, b.y, 0.0f);
    g_cp_pad[4 * i + 2] = make_float4(b.z, b.w, c.x, 0.0f);
    g_cp_pad[4 * i + 3] = make_float4(c.y, c.z, c.w, 0.0f);
}

// ---------------------------------------------------------------------------
// Main: 2 points/thread, 4 planes -> 8 independent LDG.128 gathers in flight.
// Grid 1024 keeps occupancy ~80%+ while doubling per-thread MLP vs R6.
// ---------------------------------------------------------------------------
__global__ void __launch_bounds__(256) refl_kernel(const float* __restrict__ y_pred,
                                                   const float* __restrict__ points,
                                                   float* __restrict__ out) {
    const int b  = blockIdx.x >> 5;               // 32 blocks per batch
    const int n0 = (blockIdx.x & 31) << 9;        // first of 512 points

    __shared__ float4 plane[4];                   // n_hat.xyz, d
    __shared__ float  spts[1536];                 // 512 points * xyz
    if (threadIdx.x < 4) {
        const float* yp = y_pred + (b * 4 + threadIdx.x) * 4;
        float nx = yp[0], ny = yp[1], nz = yp[2];
        float inv = rsqrtf(nx*nx + ny*ny + nz*nz);
        plane[threadIdx.x] = make_float4(nx*inv, ny*inv, nz*inv, yp[3]);
    }
    // Stage 512 points = 1536 floats = 384 float4 (16B-aligned: n0*3*4 % 16 == 0).
    {
        const float4* src = (const float4*)(points + ((size_t)b * N_ + n0) * 3);
        ((float4*)spts)[threadIdx.x] = src[threadIdx.x];
        if (threadIdx.x < 128)
            ((float4*)spts)[threadIdx.x + 256] = src[threadIdx.x + 256];
    }
    __syncthreads();

    const float4* cpb = g_cp_pad + (b << 15);     // b * 32768

    float acc = 0.0f;
#pragma unroll
    for (int k = 0; k < 2; k++) {
        const int p = threadIdx.x + (k << 8);
        const float px = spts[3 * p + 0];
        const float py = spts[3 * p + 1];
        const float pz = spts[3 * p + 2];

        float rx[4], ry[4], rz[4];
        const float4* ga[4];
#pragma unroll
        for (int c = 0; c < 4; c++) {
            float4 pl = plane[c];
            float t  = 2.0f * (px*pl.x + py*pl.y + pz*pl.z + pl.w);
            rx[c] = fmaf(-t, pl.x, px);
            ry[c] = fmaf(-t, pl.y, py);
            rz[c] = fmaf(-t, pl.z, pz);
            int v0 = min(RES_ - 1, max(0, __float2int_rd(rx[c] * (float)RES_)));
            int v1 = min(RES_ - 1, max(0, __float2int_rd(ry[c] * (float)RES_)));
            int v2 = min(RES_ - 1, max(0, __float2int_rd(rz[c] * (float)RES_)));
            ga[c] = &cpb[(v0 << 10) | (v1 << 5) | v2];
        }
        float4 cv[4];
#pragma unroll
        for (int c = 0; c < 4; c++) cv[c] = __ldg(ga[c]);
#pragma unroll
        for (int c = 0; c < 4; c++) {
            float dx = rx[c] - cv[c].x, dy = ry[c] - cv[c].y, dz = rz[c] - cv[c].z;
            acc += sqrtf(fmaf(dx, dx, fmaf(dy, dy, dz * dz)));
        }
    }

    // Deterministic block reduction (fixed order), no float atomics.
#pragma unroll
    for (int off = 16; off >= 1; off >>= 1)
        acc += __shfl_xor_sync(0xffffffffu, acc, off);
    __shared__ float ws[8];
    const int wid = threadIdx.x >> 5;
    if ((threadIdx.x & 31) == 0) ws[wid] = acc;
    __syncthreads();

    __shared__ bool is_last;
    if (threadIdx.x == 0) {
        float s = 0.0f;
#pragma unroll
        for (int w = 0; w < 8; w++) s += ws[w];
        // L2 store of the partial, then RELEASE atomic (no gpu fence / L1 flush).
        asm volatile("st.global.cg.f32 [%0], %1;"
                     :: "l"(&g_partials[blockIdx.x]), "f"(s) : "memory");
        int done;
        asm volatile("atom.release.gpu.global.add.s32 %0, [%1], 1;"
                     : "=r"(done) : "l"(&g_count) : "memory");
        is_last = (done == NB - 1);
    }
    __syncthreads();
    if (!is_last) return;

    // ---- last block only: acquire, then final deterministic reduction ----
    asm volatile("fence.acq_rel.gpu;" ::: "memory");

    // Regularizer: 25 * mean_b ||n_hat n_hat^T - I||_F  (warp 0, one lane/batch)
    __shared__ float reg_s;
    if (threadIdx.x < 32) {
        const float* yp = y_pred + threadIdx.x * 16;
        float nh[4][3];
#pragma unroll
        for (int c = 0; c < 4; c++) {
            float nx = yp[c*4+0], ny = yp[c*4+1], nz = yp[c*4+2];
            float inv = rsqrtf(nx*nx + ny*ny + nz*nz);
            nh[c][0] = nx*inv; nh[c][1] = ny*inv; nh[c][2] = nz*inv;
        }
        float s = 0.0f;
#pragma unroll
        for (int c = 0; c < 4; c++)
#pragma unroll
            for (int e = 0; e < 4; e++) {
                float g = nh[c][0]*nh[e][0] + nh[c][1]*nh[e][1] + nh[c][2]*nh[e][2]
                          - (c == e ? 1.0f : 0.0f);
                s += g * g;
            }
        float reg = sqrtf(s);
#pragma unroll
        for (int off = 16; off >= 1; off >>= 1)
            reg += __shfl_xor_sync(0xffffffffu, reg, off);
        if (threadIdx.x == 0) reg_s = 25.0f * reg * (1.0f / (float)B_);
    }

    // Sum all 1024 partials in fixed order, reading via L2 (.cg).
    __shared__ float red[256];
    float a0, a1, a2, a3;
    {
        const float* p = g_partials;
        int i = threadIdx.x;
        asm volatile("ld.global.cg.f32 %0, [%1];" : "=f"(a0) : "l"(p + i));
        asm volatile("ld.global.cg.f32 %0, [%1];" : "=f"(a1) : "l"(p + i + 256));
        asm volatile("ld.global.cg.f32 %0, [%1];" : "=f"(a2) : "l"(p + i + 512));
        asm volatile("ld.global.cg.f32 %0, [%1];" : "=f"(a3) : "l"(p + i + 768));
    }
    red[threadIdx.x] = (a0 + a1) + (a2 + a3);
    __syncthreads();
#pragma unroll
    for (int stride = 128; stride >= 1; stride >>= 1) {
        if (threadIdx.x < stride) red[threadIdx.x] += red[threadIdx.x + stride];
        __syncthreads();
    }
    if (threadIdx.x == 0) {
        out[0]  = red[0] * (1.0f / (float)N_) + reg_s;
        g_count = 0;                               // reset for next graph replay
    }
}

extern "C" void kernel_launch(void* const* d_in, const int* in_sizes, int n_in,
                              void* d_out, int out_size) {
    const float* y_pred = (const float*)d_in[0];
    const float* points = (const float*)d_in[1];
    // d_in[2] = voxel_grid — unused by the reference math.
    const float4* cp4   = (const float4*)d_in[3];
    float* out = (float*)d_out;

    pad_kernel<<<NVOX / 4 / 256, 256>>>(cp4);
    refl_kernel<<<NB, 256>>>(y_pred, points, out);
}

// round 9
// speedup vs baseline: 1.0949x; 1.0572x over previous
#include <cuda_runtime.h>

#define B_   32
#define C_   4
#define N_   16384
#define RES_ 32
#define NVOX (B_ * RES_ * RES_ * RES_)    // 1048576
#define NB   1024                         // refl blocks: 32 per batch, 512 pts each

// Scratch (allocation-free): padded float4 copy of voxel_grid_cp -> LDG.128 gathers.
__device__ float4 g_cp_pad[NVOX];         // 16 MB
__device__ float  g_partials[NB];
__device__ int    g_count = 0;            // reset to 0 by last block each run

// ---------------------------------------------------------------------------
// Pad voxel_grid_cp [B,32,32,32,3] -> float4 (4 voxels / thread, all LDG/STG.128).
// ---------------------------------------------------------------------------
__global__ void __launch_bounds__(256) pad_kernel(const float4* __restrict__ cp4) {
    int i = blockIdx.x * 256 + threadIdx.x;      // 0 .. NVOX/4-1
    float4 a = cp4[3 * i + 0];
    float4 b = cp4[3 * i + 1];
    float4 c = cp4[3 * i + 2];
    g_cp_pad[4 * i + 0] = make_float4(a.x, a.y, a.z, 0.0f);
    g_cp_pad[4 * i + 1] = make_float4(a.w, b.x, b.y, 0.0f);
    g_cp_pad[4 * i + 2] = make_float4(b.z, b.w, c.x, 0.0f);
    g_cp_pad[4 * i + 3] = make_float4(c.y, c.z, c.w, 0.0f);
}

// ---------------------------------------------------------------------------
// Main: 2 points/thread, 4 planes (ILP-8 gathers), <=32 regs so all 1024 CTAs
// are resident in ONE wave (148 SMs x 8 CTAs = 1184 slots).
// ---------------------------------------------------------------------------
__global__ void __launch_bounds__(256, 8) refl_kernel(const float* __restrict__ y_pred,
                                                      const float* __restrict__ points,
                                                      float* __restrict__ out) {
    const int b  = blockIdx.x >> 5;               // 32 blocks per batch
    const int n0 = (blockIdx.x & 31) << 9;        // first of 512 points

    __shared__ float4 plane[4];                   // n_hat.xyz, d
    __shared__ float  spts[1536];                 // 512 points * xyz
    if (threadIdx.x < 4) {
        const float* yp = y_pred + (b * 4 + threadIdx.x) * 4;
        float nx = yp[0], ny = yp[1], nz = yp[2];
        float inv = rsqrtf(nx*nx + ny*ny + nz*nz);
        plane[threadIdx.x] = make_float4(nx*inv, ny*inv, nz*inv, yp[3]);
    }
    // Stage 512 points = 1536 floats = 384 float4 (16B-aligned).
    {
        const float4* src = (const float4*)(points + ((size_t)b * N_ + n0) * 3);
        ((float4*)spts)[threadIdx.x] = src[threadIdx.x];
        if (threadIdx.x < 128)
            ((float4*)spts)[threadIdx.x + 256] = src[threadIdx.x + 256];
    }
    __syncthreads();

    const float4* cpb = g_cp_pad + (b << 15);     // b * 32768

    float acc = 0.0f;
#pragma unroll
    for (int k = 0; k < 2; k++) {
        const int p = threadIdx.x + (k << 8);
        const float px = spts[3 * p + 0];
        const float py = spts[3 * p + 1];
        const float pz = spts[3 * p + 2];

        float rx[4], ry[4], rz[4];
        int off[4];                               // 32-bit element offsets
#pragma unroll
        for (int c = 0; c < 4; c++) {
            float4 pl = plane[c];
            float t  = 2.0f * (px*pl.x + py*pl.y + pz*pl.z + pl.w);
            rx[c] = fmaf(-t, pl.x, px);
            ry[c] = fmaf(-t, pl.y, py);
            rz[c] = fmaf(-t, pl.z, pz);
            int v0 = min(RES_ - 1, max(0, __float2int_rd(rx[c] * (float)RES_)));
            int v1 = min(RES_ - 1, max(0, __float2int_rd(ry[c] * (float)RES_)));
            int v2 = min(RES_ - 1, max(0, __float2int_rd(rz[c] * (float)RES_)));
            off[c] = (v0 << 10) | (v1 << 5) | v2;
        }
        float4 cv[4];
#pragma unroll
        for (int c = 0; c < 4; c++) cv[c] = __ldg(cpb + off[c]);
#pragma unroll
        for (int c = 0; c < 4; c++) {
            float dx = rx[c] - cv[c].x, dy = ry[c] - cv[c].y, dz = rz[c] - cv[c].z;
            acc += sqrtf(fmaf(dx, dx, fmaf(dy, dy, dz * dz)));
        }
    }

    // Deterministic block reduction (fixed order), no float atomics.
#pragma unroll
    for (int off = 16; off >= 1; off >>= 1)
        acc += __shfl_xor_sync(0xffffffffu, acc, off);
    __shared__ float ws[8];
    const int wid = threadIdx.x >> 5;
    if ((threadIdx.x & 31) == 0) ws[wid] = acc;
    __syncthreads();

    __shared__ bool is_last;
    if (threadIdx.x == 0) {
        float s = 0.0f;
#pragma unroll
        for (int w = 0; w < 8; w++) s += ws[w];
        // L2 store of the partial, then RELEASE atomic (no gpu fence / L1 flush).
        asm volatile("st.global.cg.f32 [%0], %1;"
                     :: "l"(&g_partials[blockIdx.x]), "f"(s) : "memory");
        int done;
        asm volatile("atom.release.gpu.global.add.s32 %0, [%1], 1;"
                     : "=r"(done) : "l"(&g_count) : "memory");
        is_last = (done == NB - 1);
    }
    __syncthreads();
    if (!is_last) return;

    // ---- last block only: acquire, then final deterministic reduction ----
    asm volatile("fence.acq_rel.gpu;" ::: "memory");

    // Regularizer: 25 * mean_b ||n_hat n_hat^T - I||_F  (warp 0, one lane/batch)
    __shared__ float reg_s;
    if (threadIdx.x < 32) {
        const float* yp = y_pred + threadIdx.x * 16;
        float nh[4][3];
#pragma unroll
        for (int c = 0; c < 4; c++) {
            float nx = yp[c*4+0], ny = yp[c*4+1], nz = yp[c*4+2];
            float inv = rsqrtf(nx*nx + ny*ny + nz*nz);
            nh[c][0] = nx*inv; nh[c][1] = ny*inv; nh[c][2] = nz*inv;
        }
        float s = 0.0f;
#pragma unroll
        for (int c = 0; c < 4; c++)
#pragma unroll
            for (int e = 0; e < 4; e++) {
                float g = nh[c][0]*nh[e][0] + nh[c][1]*nh[e][1] + nh[c][2]*nh[e][2]
                          - (c == e ? 1.0f : 0.0f);
                s += g * g;
            }
        float reg = sqrtf(s);
#pragma unroll
        for (int off = 16; off >= 1; off >>= 1)
            reg += __shfl_xor_sync(0xffffffffu, reg, off);
        if (threadIdx.x == 0) reg_s = 25.0f * reg * (1.0f / (float)B_);
    }

    // Sum all 1024 partials in fixed order, reading via L2 (.cg).
    __shared__ float red[256];
    float a0, a1, a2, a3;
    {
        const float* p = g_partials;
        int i = threadIdx.x;
        asm volatile("ld.global.cg.f32 %0, [%1];" : "=f"(a0) : "l"(p + i));
        asm volatile("ld.global.cg.f32 %0, [%1];" : "=f"(a1) : "l"(p + i + 256));
        asm volatile("ld.global.cg.f32 %0, [%1];" : "=f"(a2) : "l"(p + i + 512));
        asm volatile("ld.global.cg.f32 %0, [%1];" : "=f"(a3) : "l"(p + i + 768));
    }
    red[threadIdx.x] = (a0 + a1) + (a2 + a3);
    __syncthreads();
#pragma unroll
    for (int stride = 128; stride >= 1; stride >>= 1) {
        if (threadIdx.x < stride) red[threadIdx.x] += red[threadIdx.x + stride];
        __syncthreads();
    }
    if (threadIdx.x == 0) {
        out[0]  = red[0] * (1.0f / (float)N_) + reg_s;
        g_count = 0;                               // reset for next graph replay
    }
}

extern "C" void kernel_launch(void* const* d_in, const int* in_sizes, int n_in,
                              void* d_out, int out_size) {
    const float* y_pred = (const float*)d_in[0];
    const float* points = (const float*)d_in[1];
    // d_in[2] = voxel_grid — unused by the reference math.
    const float4* cp4   = (const float4*)d_in[3];
    float* out = (float*)d_out;

    pad_kernel<<<NVOX / 4 / 256, 256>>>(cp4);
    refl_kernel<<<NB, 256>>>(y_pred, points, out);
}